// round 1
// baseline (speedup 1.0000x reference)
#include <cuda_runtime.h>
#include <math.h>

// Problem constants
#define B_SZ    2048
#define HDIM    1024
#define DDIM    512
#define MAXN    64
#define MID_SP  512
#define MID_CD  512
#define MID_DEC 768

// Scratch (device globals; no allocation allowed)
__device__ int   g_n[B_SZ];
__device__ float g_enc[65 * HDIM];
__device__ float g_zc[B_SZ * HDIM];

__device__ __forceinline__ float mishf(float x) {
    float sp = log1pf(expf(x));
    if (x > 20.f) sp = x;                 // overflow guard
    return x * tanhf(sp);
}

// ---------------- packed f32x2 helpers (sm_103a FFMA2) ----------------
__device__ __forceinline__ unsigned long long dup2(float x) {
    unsigned long long r;
    asm("mov.b64 %0, {%1, %1};" : "=l"(r) : "f"(x));
    return r;
}
__device__ __forceinline__ void fma2(unsigned long long& d,
                                     unsigned long long a,
                                     unsigned long long b) {
    asm("fma.rn.f32x2 %0, %1, %2, %0;" : "+l"(d) : "l"(a), "l"(b));
}
__device__ __forceinline__ float2 unpack2(unsigned long long v) {
    float2 f;
    asm("mov.b64 {%0, %1}, %2;" : "=f"(f.x), "=f"(f.y) : "l"(v));
    return f;
}

// =====================================================================
// Kernel 1: size_pred MLP -> g_n[b]
//   h = mish(LN(z @ sp_w1 + sp_b1, g, beta));  n = clip(rint(h@sp_w2+b2),0,64)
// grid 256 blocks x 256 thr, 8 batch rows per block
// =====================================================================
__global__ __launch_bounds__(256)
void size_pred_kernel(const float* __restrict__ z,
                      const float* __restrict__ w1,   // [1024,512]
                      const float* __restrict__ b1v,
                      const float* __restrict__ g,
                      const float* __restrict__ beta,
                      const float* __restrict__ w2,   // [512,1]
                      const float* __restrict__ b2v)
{
    __shared__ float z_s[8][HDIM];
    __shared__ float red1[256], red2[256];
    __shared__ float mu_s[8], rs_s[8];

    const int tid = threadIdx.x;
    const int b0  = blockIdx.x * 8;

    for (int i = tid; i < 8 * HDIM; i += 256)
        z_s[i >> 10][i & 1023] = z[(size_t)b0 * HDIM + i];
    __syncthreads();

    float pre[8][2];
#pragma unroll
    for (int r = 0; r < 8; r++) { pre[r][0] = 0.f; pre[r][1] = 0.f; }

    for (int k = 0; k < HDIM; k++) {
        float wa = w1[k * MID_SP + tid];
        float wb = w1[k * MID_SP + tid + 256];
#pragma unroll
        for (int r = 0; r < 8; r++) {
            float zv = z_s[r][k];
            pre[r][0] = fmaf(zv, wa, pre[r][0]);
            pre[r][1] = fmaf(zv, wb, pre[r][1]);
        }
    }
    float ba = b1v[tid], bb = b1v[tid + 256];
#pragma unroll
    for (int r = 0; r < 8; r++) { pre[r][0] += ba; pre[r][1] += bb; }

    // LayerNorm statistics per row (512 elems)
    for (int r = 0; r < 8; r++) {
        red1[tid] = pre[r][0] + pre[r][1];
        red2[tid] = pre[r][0] * pre[r][0] + pre[r][1] * pre[r][1];
        __syncthreads();
        for (int s = 128; s > 0; s >>= 1) {
            if (tid < s) { red1[tid] += red1[tid + s]; red2[tid] += red2[tid + s]; }
            __syncthreads();
        }
        if (tid == 0) {
            float mu  = red1[0] * (1.f / 512.f);
            float var = red2[0] * (1.f / 512.f) - mu * mu;
            mu_s[r] = mu;
            rs_s[r] = rsqrtf(var + 1e-5f);
        }
        __syncthreads();
    }

    float ga = g[tid], gb = g[tid + 256];
    float bta = beta[tid], btb = beta[tid + 256];
    float w2a = w2[tid], w2b = w2[tid + 256];

    for (int r = 0; r < 8; r++) {
        float h0 = mishf((pre[r][0] - mu_s[r]) * rs_s[r] * ga + bta);
        float h1 = mishf((pre[r][1] - mu_s[r]) * rs_s[r] * gb + btb);
        red1[tid] = h0 * w2a + h1 * w2b;
        __syncthreads();
        for (int s = 128; s > 0; s >>= 1) {
            if (tid < s) red1[tid] += red1[tid + s];
            __syncthreads();
        }
        if (tid == 0) {
            float logit = red1[0] + b2v[0];
            int n = (int)rintf(logit);      // round-half-even, matches jnp.round
            n = min(max(n, 0), MAXN);
            g_n[b0 + r] = n;
        }
        __syncthreads();
    }
}

// =====================================================================
// Kernel 2: cardinality table for all 65 possible n values
//   g_enc[v,:] = mish(v*cd_w1 + cd_b1) @ cd_w2 + cd_b2
// =====================================================================
__global__ __launch_bounds__(256)
void enc_kernel(const float* __restrict__ cw1, const float* __restrict__ cb1,
                const float* __restrict__ cw2, const float* __restrict__ cb2)
{
    __shared__ float m_s[MID_CD];
    const int v = blockIdx.x;           // 0..64
    const int tid = threadIdx.x;

    for (int j = tid; j < MID_CD; j += 256)
        m_s[j] = mishf((float)v * cw1[j] + cb1[j]);
    __syncthreads();

    for (int j = tid; j < HDIM; j += 256) {
        float acc = cb2[j];
        for (int m = 0; m < MID_CD; m++)
            acc = fmaf(m_s[m], cw2[m * HDIM + j], acc);
        g_enc[v * HDIM + j] = acc;
    }
}

// =====================================================================
// Kernel 3: zc = z - enc_table[n[b]]
// =====================================================================
__global__ __launch_bounds__(256)
void zc_kernel(const float* __restrict__ z)
{
    int idx = blockIdx.x * 256 + threadIdx.x;   // 2048*1024 total
    int b = idx >> 10, i = idx & 1023;
    g_zc[idx] = z[idx] - g_enc[g_n[b] * HDIM + i];
}

// =====================================================================
// Kernel 4: fused decoder.
//   Per block: 16 rows (fixed batch b, k0..k0+15).
//   Phase 1: t[16,768] = mish( (zc[b] (*) key[k]) @ W1 + b1 )   (A in smem)
//   Phase 2: out[16,512] = t @ W2 + b2, masked write
// 256 threads. Dynamic smem ~176KB.
// =====================================================================
#define AST 20   // padded row stride (floats) for a_s/t_s, 16B-aligned float4 at r0=4*ty

__global__ __launch_bounds__(256)
void decoder_kernel(const float* __restrict__ key,
                    const float* __restrict__ W1, const float* __restrict__ b1,
                    const float* __restrict__ W2, const float* __restrict__ b2,
                    float* __restrict__ out)
{
    const int blk = blockIdx.x;        // 8192 = 2048 batches * 4 row-tiles
    const int b   = blk >> 2;
    const int k0  = (blk & 3) * 16;
    const int n   = g_n[b];
    const int tid = threadIdx.x;

    float* outrow = out + ((size_t)b * MAXN + k0) * DDIM;

    if (k0 >= n) {   // whole tile masked: zero-fill and exit (uniform branch)
        float4 zf = make_float4(0.f, 0.f, 0.f, 0.f);
        float4* o4 = (float4*)outrow;
        for (int i = tid; i < 16 * DDIM / 4; i += 256) o4[i] = zf;
        return;
    }

    extern __shared__ float smem[];
    float* zc_s = smem;                       // 1024
    float* a_s  = zc_s + HDIM;                // 1024 * 20
    float* t_s  = a_s  + HDIM * AST;          // 768 * 20
    float* w_s  = t_s  + MID_DEC * AST;       // 32 * 256

    // stage zc row
    for (int i = tid; i < HDIM; i += 256) zc_s[i] = g_zc[(size_t)b * HDIM + i];
    __syncthreads();

    // stage A^T: a_s[k][r] = zc[k] * key[k0+r][k]
    for (int r = 0; r < 16; r++) {
        const float* kr = key + (size_t)(k0 + r) * HDIM;
        for (int k = tid; k < HDIM; k += 256)
            a_s[k * AST + r] = zc_s[k] * kr[k];
    }
    __syncthreads();

    const int tx = tid & 63;           // 64 col-groups
    const int ty = tid >> 6;           // 4 row-groups
    const int r0 = ty * 4;
    const int c4 = tx * 4;

    // ---------------- Phase 1: 768 output cols in 3 tiles of 256 ----------------
    for (int ct = 0; ct < 3; ct++) {
        const int cbase = ct * 256;
        unsigned long long acc2[4][2];
#pragma unroll
        for (int i = 0; i < 4; i++) { acc2[i][0] = 0ull; acc2[i][1] = 0ull; }

        for (int kk = 0; kk < HDIM; kk += 32) {
            // stage W1 tile [32][256]
#pragma unroll
            for (int i = 0; i < 8; i++) {
                int e   = tid + i * 256;
                int row = e >> 6;
                int col = (e & 63) * 4;
                *(float4*)&w_s[row * 256 + col] =
                    *(const float4*)&W1[(size_t)(kk + row) * MID_DEC + cbase + col];
            }
            __syncthreads();
#pragma unroll
            for (int k = 0; k < 32; k++) {
                float4 av = *(const float4*)&a_s[(kk + k) * AST + r0];   // broadcast
                ulonglong2 wv = *(const ulonglong2*)&w_s[k * 256 + c4];
                unsigned long long a0 = dup2(av.x), a1 = dup2(av.y);
                unsigned long long a2 = dup2(av.z), a3 = dup2(av.w);
                fma2(acc2[0][0], a0, wv.x); fma2(acc2[0][1], a0, wv.y);
                fma2(acc2[1][0], a1, wv.x); fma2(acc2[1][1], a1, wv.y);
                fma2(acc2[2][0], a2, wv.x); fma2(acc2[2][1], a2, wv.y);
                fma2(acc2[3][0], a3, wv.x); fma2(acc2[3][1], a3, wv.y);
            }
            __syncthreads();
        }
        // epilogue: +bias, mish, store transposed into t_s
        float accf[4][4];
#pragma unroll
        for (int i = 0; i < 4; i++) {
            float2 u0 = unpack2(acc2[i][0]);
            float2 u1 = unpack2(acc2[i][1]);
            accf[i][0] = u0.x; accf[i][1] = u0.y; accf[i][2] = u1.x; accf[i][3] = u1.y;
        }
#pragma unroll
        for (int j = 0; j < 4; j++) {
            int col = cbase + c4 + j;
            float bb = b1[col];
            float4 v;
            v.x = mishf(accf[0][j] + bb);
            v.y = mishf(accf[1][j] + bb);
            v.z = mishf(accf[2][j] + bb);
            v.w = mishf(accf[3][j] + bb);
            *(float4*)&t_s[col * AST + r0] = v;
        }
    }
    __syncthreads();

    // ---------------- Phase 2: 512 output cols in 2 tiles of 256 ----------------
    for (int ct = 0; ct < 2; ct++) {
        const int cbase = ct * 256;
        unsigned long long acc2[4][2];
#pragma unroll
        for (int i = 0; i < 4; i++) { acc2[i][0] = 0ull; acc2[i][1] = 0ull; }

        for (int kk = 0; kk < MID_DEC; kk += 32) {
#pragma unroll
            for (int i = 0; i < 8; i++) {
                int e   = tid + i * 256;
                int row = e >> 6;
                int col = (e & 63) * 4;
                *(float4*)&w_s[row * 256 + col] =
                    *(const float4*)&W2[(size_t)(kk + row) * DDIM + cbase + col];
            }
            __syncthreads();
#pragma unroll
            for (int k = 0; k < 32; k++) {
                float4 av = *(const float4*)&t_s[(kk + k) * AST + r0];
                ulonglong2 wv = *(const ulonglong2*)&w_s[k * 256 + c4];
                unsigned long long a0 = dup2(av.x), a1 = dup2(av.y);
                unsigned long long a2 = dup2(av.z), a3 = dup2(av.w);
                fma2(acc2[0][0], a0, wv.x); fma2(acc2[0][1], a0, wv.y);
                fma2(acc2[1][0], a1, wv.x); fma2(acc2[1][1], a1, wv.y);
                fma2(acc2[2][0], a2, wv.x); fma2(acc2[2][1], a2, wv.y);
                fma2(acc2[3][0], a3, wv.x); fma2(acc2[3][1], a3, wv.y);
            }
            __syncthreads();
        }
        float accf[4][4];
#pragma unroll
        for (int i = 0; i < 4; i++) {
            float2 u0 = unpack2(acc2[i][0]);
            float2 u1 = unpack2(acc2[i][1]);
            accf[i][0] = u0.x; accf[i][1] = u0.y; accf[i][2] = u1.x; accf[i][3] = u1.y;
        }
#pragma unroll
        for (int i = 0; i < 4; i++) {
            int r = r0 + i;
            bool valid = (k0 + r) < n;
            int col = cbase + c4;
            float4 v;
            v.x = valid ? accf[i][0] + b2[col + 0] : 0.f;
            v.y = valid ? accf[i][1] + b2[col + 1] : 0.f;
            v.z = valid ? accf[i][2] + b2[col + 2] : 0.f;
            v.w = valid ? accf[i][3] + b2[col + 3] : 0.f;
            *(float4*)&outrow[(size_t)r * DDIM + col] = v;
        }
    }
}

// =====================================================================
// Kernel 5: batch indices output (float), appended after x if room
// =====================================================================
__global__ __launch_bounds__(256)
void batch_kernel(float* __restrict__ outb)
{
    int idx = blockIdx.x * 256 + threadIdx.x;   // 131072
    int b = idx >> 6, k = idx & 63;
    outb[idx] = (k < g_n[b]) ? (float)b : -1.0f;
}

// =====================================================================
extern "C" void kernel_launch(void* const* d_in, const int* in_sizes, int n_in,
                              void* d_out, int out_size)
{
    const float* z      = (const float*)d_in[0];
    const float* key    = (const float*)d_in[1];
    const float* sp_w1  = (const float*)d_in[2];
    const float* sp_b1  = (const float*)d_in[3];
    const float* sp_g   = (const float*)d_in[4];
    const float* sp_bt  = (const float*)d_in[5];
    const float* sp_w2  = (const float*)d_in[6];
    const float* sp_b2  = (const float*)d_in[7];
    const float* cd_w1  = (const float*)d_in[8];
    const float* cd_b1  = (const float*)d_in[9];
    const float* cd_w2  = (const float*)d_in[10];
    const float* cd_b2  = (const float*)d_in[11];
    const float* dec_w1 = (const float*)d_in[12];
    const float* dec_b1 = (const float*)d_in[13];
    const float* dec_w2 = (const float*)d_in[14];
    const float* dec_b2 = (const float*)d_in[15];
    float* out = (float*)d_out;

    const int SMEM_BYTES = (HDIM + HDIM * AST + MID_DEC * AST + 32 * 256) * sizeof(float);
    cudaFuncSetAttribute(decoder_kernel,
                         cudaFuncAttributeMaxDynamicSharedMemorySize, SMEM_BYTES);

    size_pred_kernel<<<B_SZ / 8, 256>>>(z, sp_w1, sp_b1, sp_g, sp_bt, sp_w2, sp_b2);
    enc_kernel<<<65, 256>>>(cd_w1, cd_b1, cd_w2, cd_b2);
    zc_kernel<<<(B_SZ * HDIM) / 256, 256>>>(z);
    decoder_kernel<<<B_SZ * 4, 256, SMEM_BYTES>>>(key, dec_w1, dec_b1, dec_w2, dec_b2, out);

    long long x_elems = (long long)B_SZ * MAXN * DDIM;   // 67,108,864
    if ((long long)out_size >= x_elems + (long long)B_SZ * MAXN)
        batch_kernel<<<(B_SZ * MAXN) / 256, 256>>>(out + x_elems);
}